// round 6
// baseline (speedup 1.0000x reference)
#include <cuda_runtime.h>
#include <cstdint>

#define E_CNT   300000
#define MTILE   64
#define NTH     256
#define NCTA    ((E_CNT + MTILE - 1) / MTILE)

// ---- strides (floats) ----
#define SA1  20     // A tile rows (16 k + pad)
#define SB1T 20     // B1 n-major rows (16 k + pad)
#define SB2T 20
#define SH   260    // H rows (256 k + pad)
#define SOS  132

// ---- smem byte offsets ----
#define SM_IDX   0                  // 128 ints = 512
#define SM_PAR   512                // 640 floats -> ends 3072
#define SM_B2    3072               // 3 x 128*20*4 = 30720 -> ends 33792
#define SM_U     33792
#define OFF_A1   0                  // 3 x 64*20*4  = 15360
#define OFF_B1   15360              // 3 x 256*20*4 = 61440 -> ends 76800
#define A1_BUF   5120
#define B1_BUF   20480
#define B2_BUF   10240
#define SM_TOTAL 110592             // 33792 + 76800 (H 64*260*4=66560 fits union)

// pre-rounded (tf32) copies; weights pre-TRANSPOSED to n-major
__device__ float g_W1t[256 * 384];   // [n][k]
__device__ float g_W2t[128 * 256];   // [n][k]
__device__ float g_noder[50000 * 128];

static __device__ __forceinline__ uint32_t tf32r(float f) {
    uint32_t r; asm("cvt.rna.tf32.f32 %0, %1;" : "=r"(r) : "f"(f)); return r;
}
static __device__ __forceinline__ uint32_t smem_u32(const void* p) {
    uint32_t a;
    asm("{ .reg .u64 t; cvta.to.shared.u64 t, %1; cvt.u32.u64 %0, t; }" : "=r"(a) : "l"(p));
    return a;
}
static __device__ __forceinline__ void cp16(uint32_t dst, const void* src) {
    asm volatile("cp.async.cg.shared.global [%0], [%1], 16;" :: "r"(dst), "l"(src));
}
#define CP_COMMIT() asm volatile("cp.async.commit_group;" ::: "memory")
#define CP_WAIT(n)  asm volatile("cp.async.wait_group %0;" :: "n"(n) : "memory")

#define LDSM4(r, addr)                                                        \
    asm volatile("ldmatrix.sync.aligned.m8n8.x4.shared.b16 {%0,%1,%2,%3}, [%4];" \
        : "=r"((r)[0]), "=r"((r)[1]), "=r"((r)[2]), "=r"((r)[3]) : "r"(addr))

#define MMA_TF32(d, a, b)                                                     \
    asm volatile("mma.sync.aligned.m16n8k8.row.col.f32.tf32.tf32.f32 "        \
        "{%0,%1,%2,%3}, {%4,%5,%6,%7}, {%8,%9}, {%0,%1,%2,%3};"               \
        : "+f"((d)[0]), "+f"((d)[1]), "+f"((d)[2]), "+f"((d)[3])              \
        : "r"((a)[0]), "r"((a)[1]), "r"((a)[2]), "r"((a)[3]),                 \
          "r"((b)[0]), "r"((b)[1]))

// ---------------- prep: tf32-round node table; round+transpose weights ----------------
__global__ void prep_kernel(const float* __restrict__ W1,
                            const float* __restrict__ W2,
                            const float* __restrict__ nat) {
    int t = blockIdx.x * blockDim.x + threadIdx.x;
    int stride = gridDim.x * blockDim.x;
    const int NW1 = 384 * 256, NW2 = 256 * 128, NND = 50000 * 128 / 4;
    for (int i = t; i < NW1; i += stride) {
        int k = i >> 8, n = i & 255;
        ((uint32_t*)g_W1t)[n * 384 + k] = tf32r(W1[i]);
    }
    for (int i = t; i < NW2; i += stride) {
        int k = i >> 7, n = i & 127;
        ((uint32_t*)g_W2t)[n * 256 + k] = tf32r(W2[i]);
    }
    for (int i = t; i < NND; i += stride) {
        float4 v = ((const float4*)nat)[i];
        uint4 u = { tf32r(v.x), tf32r(v.y), tf32r(v.z), tf32r(v.w) };
        ((uint4*)g_noder)[i] = u;
    }
}

// ---------------- fused edge MLP ----------------
__global__ void __launch_bounds__(NTH, 2)
edge_mlp_kernel(const float* __restrict__ edge_attr,
                const int*   __restrict__ edge_index,
                const float* __restrict__ b1,
                const float* __restrict__ b2,
                const float* __restrict__ gamma_,
                const float* __restrict__ beta_,
                float* __restrict__ out)
{
    extern __shared__ char smem[];
    const uint32_t sb = smem_u32(smem);
    const int tid = threadIdx.x;
    const int wid = tid >> 5, lid = tid & 31;
    const int g = lid >> 2, t4 = lid & 3;
    const int ebase = blockIdx.x * MTILE;

    // ldmatrix per-thread selectors (matrix id = lid>>3)
    const int sel = lid >> 3;
    const int arow = (sel & 1) * 8 + (lid & 7);
    const int acol = (sel >> 1) * 4;
    const int brow = (sel >> 1) * 8 + (lid & 7);
    const int bcol = (sel & 1) * 4;

    int*   sidx = (int*)(smem + SM_IDX);
    float* P    = (float*)(smem + SM_PAR);

    {
        if (tid < 128) {
            int r = tid & 63, half = tid >> 6;
            int e = ebase + r; if (e >= E_CNT) e = E_CNT - 1;
            sidx[half * 64 + r] = edge_index[half * E_CNT + e];
        }
        P[tid] = b1[tid];
        if (tid < 128) {
            P[256 + tid] = b2[tid];
            P[384 + tid] = gamma_[tid];
            P[512 + tid] = beta_[tid];
        }
    }
    __syncthreads();

    const int mb  = (wid >> 2) * 32;   // 2 warps along M (tile 32)
    const int nb1 = (wid & 3) * 64;    // GEMM1: 4 warps along N (tile 64)
    const int nb2 = (wid & 3) * 32;    // GEMM2: tile 32

    auto issue1 = [&](int kc) {
        int buf = kc % 3;
        int src = kc >> 3, koff = (kc & 7) * 16;
        uint32_t abase = sb + SM_U + OFF_A1 + (uint32_t)buf * A1_BUF;
        uint32_t bbase = sb + SM_U + OFF_B1 + (uint32_t)buf * B1_BUF;
        {   // A: 64 rows x 4 float4 = 256 -> 1 per thread
            int r = tid >> 2, c4 = tid & 3;
            const float* sp;
            if (src == 0)      sp = g_noder + (size_t)sidx[r] * 128 + koff;
            else if (src == 1) sp = g_noder + (size_t)sidx[64 + r] * 128 + koff;
            else { int e = ebase + r; if (e >= E_CNT) e = E_CNT - 1;
                   sp = edge_attr + (size_t)e * 128 + koff; }
            cp16(abase + (uint32_t)(r * SA1 + c4 * 4) * 4, sp + c4 * 4);
        }
        #pragma unroll
        for (int i = 0; i < 4; i++) {   // B1t: 256 rows x 4 = 1024 -> 4 per thread
            int f = tid + i * NTH;
            int n = f >> 2, c4 = f & 3;
            cp16(bbase + (uint32_t)(n * SB1T + c4 * 4) * 4,
                 g_W1t + (size_t)n * 384 + kc * 16 + c4 * 4);
        }
        CP_COMMIT();
    };
    auto issue2 = [&](int kc) {
        int buf = kc % 3;
        uint32_t bbase = sb + SM_B2 + (uint32_t)buf * B2_BUF;
        #pragma unroll
        for (int i = 0; i < 2; i++) {   // B2t: 128 rows x 4 = 512 -> 2 per thread
            int f = tid + i * NTH;
            int n = f >> 2, c4 = f & 3;
            cp16(bbase + (uint32_t)(n * SB2T + c4 * 4) * 4,
                 g_W2t + (size_t)n * 256 + kc * 16 + c4 * 4);
        }
        CP_COMMIT();
    };

    // =================== GEMM1: H = relu(X @ W1 + b1) ===================
    float acc1[2][8][4];
    #pragma unroll
    for (int mi = 0; mi < 2; mi++)
        #pragma unroll
        for (int ni = 0; ni < 8; ni++)
            #pragma unroll
            for (int r = 0; r < 4; r++) acc1[mi][ni][r] = 0.0f;

    issue1(0); issue1(1);
    for (int kc = 0; kc < 24; kc++) {
        if (kc < 23) CP_WAIT(1); else CP_WAIT(0);
        __syncthreads();
        if (kc + 2 < 24) issue1(kc + 2);
        {
            const uint32_t Ab = sb + SM_U + OFF_A1 + (uint32_t)(kc % 3) * A1_BUF;
            const uint32_t Bb = sb + SM_U + OFF_B1 + (uint32_t)(kc % 3) * B1_BUF;
            #pragma unroll
            for (int ks = 0; ks < 2; ks++) {
                int k0 = ks * 8;
                uint32_t a[2][4];
                #pragma unroll
                for (int mi = 0; mi < 2; mi++) {
                    uint32_t ad = Ab + (uint32_t)((mb + mi * 16 + arow) * SA1 + k0 + acol) * 4;
                    LDSM4(a[mi], ad);
                }
                uint32_t b[8][2];
                #pragma unroll
                for (int p = 0; p < 4; p++) {
                    uint32_t r4[4];
                    uint32_t bd = Bb + (uint32_t)((nb1 + p * 16 + brow) * SB1T + k0 + bcol) * 4;
                    LDSM4(r4, bd);
                    b[2 * p][0] = r4[0]; b[2 * p][1] = r4[1];
                    b[2 * p + 1][0] = r4[2]; b[2 * p + 1][1] = r4[3];
                }
                #pragma unroll
                for (int mi = 0; mi < 2; mi++)
                    #pragma unroll
                    for (int ni = 0; ni < 8; ni++)
                        MMA_TF32(acc1[mi][ni], a[mi], b[ni]);
            }
        }
    }
    __syncthreads();

    // prefetch W2; write H (tf32) over A1/B1 region
    issue2(0); issue2(1);
    {
        float* Hs = (float*)(smem + SM_U);
        #pragma unroll
        for (int mi = 0; mi < 2; mi++) {
            #pragma unroll
            for (int ni = 0; ni < 8; ni++) {
                int k  = nb1 + ni * 8 + 2 * t4;
                int m0 = mb + mi * 16 + g;
                float v0 = fmaxf(acc1[mi][ni][0] + P[k],     0.0f);
                float v1 = fmaxf(acc1[mi][ni][1] + P[k + 1], 0.0f);
                float v2 = fmaxf(acc1[mi][ni][2] + P[k],     0.0f);
                float v3 = fmaxf(acc1[mi][ni][3] + P[k + 1], 0.0f);
                uint2 u0 = { tf32r(v0), tf32r(v1) };
                uint2 u1 = { tf32r(v2), tf32r(v3) };
                *(uint2*)&Hs[m0 * SH + k]       = u0;
                *(uint2*)&Hs[(m0 + 8) * SH + k] = u1;
            }
        }
    }
    __syncthreads();

    // =================== GEMM2: O = H @ W2 ===================
    float acc2[2][4][4];
    #pragma unroll
    for (int mi = 0; mi < 2; mi++)
        #pragma unroll
        for (int ni = 0; ni < 4; ni++)
            #pragma unroll
            for (int r = 0; r < 4; r++) acc2[mi][ni][r] = 0.0f;

    const uint32_t Hb = sb + SM_U;
    for (int kc = 0; kc < 16; kc++) {
        if (kc < 15) CP_WAIT(1); else CP_WAIT(0);
        __syncthreads();
        if (kc + 2 < 16) issue2(kc + 2);
        {
            const uint32_t Bb = sb + SM_B2 + (uint32_t)(kc % 3) * B2_BUF;
            #pragma unroll
            for (int ks = 0; ks < 2; ks++) {
                int k0g = kc * 16 + ks * 8;
                int k0  = ks * 8;
                uint32_t a[2][4];
                #pragma unroll
                for (int mi = 0; mi < 2; mi++) {
                    uint32_t ad = Hb + (uint32_t)((mb + mi * 16 + arow) * SH + k0g + acol) * 4;
                    LDSM4(a[mi], ad);
                }
                uint32_t b[4][2];
                #pragma unroll
                for (int p = 0; p < 2; p++) {
                    uint32_t r4[4];
                    uint32_t bd = Bb + (uint32_t)((nb2 + p * 16 + brow) * SB2T + k0 + bcol) * 4;
                    LDSM4(r4, bd);
                    b[2 * p][0] = r4[0]; b[2 * p][1] = r4[1];
                    b[2 * p + 1][0] = r4[2]; b[2 * p + 1][1] = r4[3];
                }
                #pragma unroll
                for (int mi = 0; mi < 2; mi++)
                    #pragma unroll
                    for (int ni = 0; ni < 4; ni++)
                        MMA_TF32(acc2[mi][ni], a[mi], b[ni]);
            }
        }
    }
    __syncthreads();  // H dead; Os reuses region

    // =================== Epilogue: +b2, LayerNorm, store ===================
    float* Os = (float*)(smem + SM_U);
    #pragma unroll
    for (int mi = 0; mi < 2; mi++) {
        #pragma unroll
        for (int ni = 0; ni < 4; ni++) {
            int c  = nb2 + ni * 8 + 2 * t4;
            int m0 = mb + mi * 16 + g;
            *(float2*)&Os[m0 * SOS + c]       = make_float2(acc2[mi][ni][0], acc2[mi][ni][1]);
            *(float2*)&Os[(m0 + 8) * SOS + c] = make_float2(acc2[mi][ni][2], acc2[mi][ni][3]);
        }
    }
    __syncthreads();

    // LayerNorm: 4 threads per row (64 rows), quad shuffle reduce
    {
        int row = tid >> 2, q = tid & 3;
        float vals[32];
        float sum = 0.0f, sq = 0.0f;
        #pragma unroll
        for (int c4 = 0; c4 < 8; c4++) {
            int cb = q * 32 + c4 * 4;
            float4 v = *(float4*)&Os[row * SOS + cb];
            v.x += P[256 + cb + 0]; v.y += P[256 + cb + 1];
            v.z += P[256 + cb + 2]; v.w += P[256 + cb + 3];
            vals[c4 * 4 + 0] = v.x; vals[c4 * 4 + 1] = v.y;
            vals[c4 * 4 + 2] = v.z; vals[c4 * 4 + 3] = v.w;
            sum += v.x + v.y + v.z + v.w;
            sq  += v.x * v.x + v.y * v.y + v.z * v.z + v.w * v.w;
        }
        sum += __shfl_xor_sync(0xFFFFFFFF, sum, 1);
        sq  += __shfl_xor_sync(0xFFFFFFFF, sq,  1);
        sum += __shfl_xor_sync(0xFFFFFFFF, sum, 2);
        sq  += __shfl_xor_sync(0xFFFFFFFF, sq,  2);
        float mu  = sum * (1.0f / 128.0f);
        float var = sq * (1.0f / 128.0f) - mu * mu;
        float rs  = rsqrtf(var + 1e-5f);
        #pragma unroll
        for (int c4 = 0; c4 < 8; c4++) {
            int cb = q * 32 + c4 * 4;
            float4 w;
            w.x = (vals[c4 * 4 + 0] - mu) * rs * P[384 + cb + 0] + P[512 + cb + 0];
            w.y = (vals[c4 * 4 + 1] - mu) * rs * P[384 + cb + 1] + P[512 + cb + 1];
            w.z = (vals[c4 * 4 + 2] - mu) * rs * P[384 + cb + 2] + P[512 + cb + 2];
            w.w = (vals[c4 * 4 + 3] - mu) * rs * P[384 + cb + 3] + P[512 + cb + 3];
            *(float4*)&Os[row * SOS + cb] = w;
        }
    }
    __syncthreads();

    // coalesced float4 store: 64 rows x 32 float4
    {
        float4* o4 = (float4*)out;
        #pragma unroll
        for (int i = 0; i < 8; i++) {
            int f = tid + i * NTH;
            int row = f >> 5, c4 = f & 31;
            int e = ebase + row;
            if (e < E_CNT)
                o4[(size_t)e * 32 + c4] = *(float4*)&Os[row * SOS + c4 * 4];
        }
    }
}

extern "C" void kernel_launch(void* const* d_in, const int* in_sizes, int n_in,
                              void* d_out, int out_size) {
    const float* node_attr = (const float*)d_in[0];
    const float* edge_attr = (const float*)d_in[1];
    const int*   edge_idx  = (const int*)d_in[2];
    const float* W1 = (const float*)d_in[3];
    const float* b1 = (const float*)d_in[4];
    const float* W2 = (const float*)d_in[5];
    const float* b2 = (const float*)d_in[6];
    const float* g  = (const float*)d_in[7];
    const float* be = (const float*)d_in[8];
    float* out = (float*)d_out;

    prep_kernel<<<960, 256>>>(W1, W2, node_attr);

    cudaFuncSetAttribute(edge_mlp_kernel,
                         cudaFuncAttributeMaxDynamicSharedMemorySize, SM_TOTAL);
    edge_mlp_kernel<<<NCTA, NTH, SM_TOTAL>>>(edge_attr, edge_idx, b1, b2, g, be, out);
}

// round 7
// speedup vs baseline: 1.6586x; 1.6586x over previous
#include <cuda_runtime.h>
#include <cuda_fp16.h>
#include <cstdint>

#define E_CNT   300000
#define MTILE   64
#define NTH     256
#define NCTA    ((E_CNT + MTILE - 1) / MTILE)

// ---- strides ----
#define SA   40     // A rows, halfwords (32 k + pad), 80B = 5x16B
#define SB1T 40
#define SB2T 40
#define SH   264    // H rows, halfwords (256 k + pad), 528B = 33x16B
#define SOS  132    // epilogue staging, floats

// ---- smem byte offsets ----
#define SM_IDX   0                  // 128 ints = 512
#define SM_PAR   512                // 640 floats -> ends 3072
#define SM_B2    3072               // 3 x 128*40*2 = 30720 -> ends 33792
#define SM_U     33792
#define OFF_A1   0                  // 3 x 64*40*2  = 15360
#define OFF_B1   15360              // 3 x 256*40*2 = 61440 -> ends 76800
#define A1_BUF   5120
#define B1_BUF   20480
#define B2_BUF   10240
#define SM_TOTAL 110592             // 33792 + 76800 ; x2 CTAs = 221184 <= 228KB

// fp16 scratch: weights pre-transposed to n-major
__device__ __half g_W1h[256 * 384];      // [n][k]
__device__ __half g_W2h[128 * 256];      // [n][k]
__device__ __half g_node16[50000 * 128];
__device__ __half g_edge16[300000 * 128];

static __device__ __forceinline__ uint32_t smem_u32(const void* p) {
    uint32_t a;
    asm("{ .reg .u64 t; cvta.to.shared.u64 t, %1; cvt.u32.u64 %0, t; }" : "=r"(a) : "l"(p));
    return a;
}
static __device__ __forceinline__ void cp16(uint32_t dst, const void* src) {
    asm volatile("cp.async.cg.shared.global [%0], [%1], 16;" :: "r"(dst), "l"(src));
}
#define CP_COMMIT() asm volatile("cp.async.commit_group;" ::: "memory")
#define CP_WAIT(n)  asm volatile("cp.async.wait_group %0;" :: "n"(n) : "memory")

#define LDSM4(r, addr)                                                        \
    asm volatile("ldmatrix.sync.aligned.m8n8.x4.shared.b16 {%0,%1,%2,%3}, [%4];" \
        : "=r"((r)[0]), "=r"((r)[1]), "=r"((r)[2]), "=r"((r)[3]) : "r"(addr))

#define MMA_F16(d, a, b)                                                      \
    asm volatile("mma.sync.aligned.m16n8k16.row.col.f32.f16.f16.f32 "         \
        "{%0,%1,%2,%3}, {%4,%5,%6,%7}, {%8,%9}, {%0,%1,%2,%3};"               \
        : "+f"((d)[0]), "+f"((d)[1]), "+f"((d)[2]), "+f"((d)[3])              \
        : "r"((a)[0]), "r"((a)[1]), "r"((a)[2]), "r"((a)[3]),                 \
          "r"((b)[0]), "r"((b)[1]))

// ---------------- prep: fp16-convert node/edge tables; convert+transpose weights ----------------
__global__ void __launch_bounds__(256)
prep_kernel(const float* __restrict__ W1,
            const float* __restrict__ W2,
            const float* __restrict__ nat,
            const float* __restrict__ eat) {
    int t = blockIdx.x * blockDim.x + threadIdx.x;
    int stride = gridDim.x * blockDim.x;
    const int NW1 = 384 * 256, NW2 = 256 * 128;
    const int NND = 50000 * 128 / 4, NED = 300000 * 128 / 4;
    for (int i = t; i < NW1; i += stride) {
        int k = i >> 8, n = i & 255;
        g_W1h[n * 384 + k] = __float2half_rn(W1[i]);
    }
    for (int i = t; i < NW2; i += stride) {
        int k = i >> 7, n = i & 127;
        g_W2h[n * 256 + k] = __float2half_rn(W2[i]);
    }
    for (int i = t; i < NND; i += stride) {
        float4 v = ((const float4*)nat)[i];
        __half2 h0 = __floats2half2_rn(v.x, v.y);
        __half2 h1 = __floats2half2_rn(v.z, v.w);
        uint2 u = { *(uint32_t*)&h0, *(uint32_t*)&h1 };
        ((uint2*)g_node16)[i] = u;
    }
    for (int i = t; i < NED; i += stride) {
        float4 v = ((const float4*)eat)[i];
        __half2 h0 = __floats2half2_rn(v.x, v.y);
        __half2 h1 = __floats2half2_rn(v.z, v.w);
        uint2 u = { *(uint32_t*)&h0, *(uint32_t*)&h1 };
        ((uint2*)g_edge16)[i] = u;
    }
}

// ---------------- fused edge MLP (fp16 tensor path) ----------------
__global__ void __launch_bounds__(NTH, 2)
edge_mlp_kernel(const int*   __restrict__ edge_index,
                const float* __restrict__ b1,
                const float* __restrict__ b2,
                const float* __restrict__ gamma_,
                const float* __restrict__ beta_,
                float* __restrict__ out)
{
    extern __shared__ char smem[];
    const uint32_t sb = smem_u32(smem);
    const int tid = threadIdx.x;
    const int wid = tid >> 5, lid = tid & 31;
    const int g = lid >> 2, t4 = lid & 3;
    const int ebase = blockIdx.x * MTILE;

    // ldmatrix selectors (tile id = lid>>3)
    const int sel  = lid >> 3;
    const int arow = (sel & 1) * 8 + (lid & 7);   // A: m-half
    const int akh  = (sel >> 1) * 8;              // A: k-half (halfwords)
    const int brow = (sel >> 1) * 8 + (lid & 7);  // B: n-half
    const int bkh  = (sel & 1) * 8;               // B: k-half

    int*   sidx = (int*)(smem + SM_IDX);
    float* P    = (float*)(smem + SM_PAR);

    {
        if (tid < 128) {
            int r = tid & 63, half = tid >> 6;
            int e = ebase + r; if (e >= E_CNT) e = E_CNT - 1;
            sidx[half * 64 + r] = edge_index[half * E_CNT + e];
        }
        P[tid] = b1[tid];
        if (tid < 128) {
            P[256 + tid] = b2[tid];
            P[384 + tid] = gamma_[tid];
            P[512 + tid] = beta_[tid];
        }
    }
    __syncthreads();

    const int mb  = (wid >> 2) * 32;   // 2 warps along M (tile 32)
    const int nb1 = (wid & 3) * 64;    // GEMM1: 4 warps along N (tile 64)
    const int nb2 = (wid & 3) * 32;    // GEMM2: tile 32

    auto issue1 = [&](int kc) {
        int buf = kc % 3;
        int src = kc >> 2, koff = (kc & 3) * 32;
        uint32_t abase = sb + SM_U + OFF_A1 + (uint32_t)buf * A1_BUF;
        uint32_t bbase = sb + SM_U + OFF_B1 + (uint32_t)buf * B1_BUF;
        {   // A: 64 rows x 4 x 16B = 256 -> 1 per thread
            int r = tid >> 2, c = tid & 3;
            const __half* sp;
            if (src == 0)      sp = g_node16 + (size_t)sidx[r] * 128 + koff;
            else if (src == 1) sp = g_node16 + (size_t)sidx[64 + r] * 128 + koff;
            else { int e = ebase + r; if (e >= E_CNT) e = E_CNT - 1;
                   sp = g_edge16 + (size_t)e * 128 + koff; }
            cp16(abase + (uint32_t)(r * SA + c * 8) * 2, sp + c * 8);
        }
        #pragma unroll
        for (int i = 0; i < 4; i++) {   // B1: 256 rows x 4 x 16B -> 4 per thread
            int f = tid + i * NTH;
            int n = f >> 2, c = f & 3;
            cp16(bbase + (uint32_t)(n * SB1T + c * 8) * 2,
                 g_W1h + (size_t)n * 384 + kc * 32 + c * 8);
        }
        CP_COMMIT();
    };
    auto issue2 = [&](int kc) {
        int buf = kc % 3;
        uint32_t bbase = sb + SM_B2 + (uint32_t)buf * B2_BUF;
        #pragma unroll
        for (int i = 0; i < 2; i++) {   // B2: 128 rows x 4 x 16B -> 2 per thread
            int f = tid + i * NTH;
            int n = f >> 2, c = f & 3;
            cp16(bbase + (uint32_t)(n * SB2T + c * 8) * 2,
                 g_W2h + (size_t)n * 256 + kc * 32 + c * 8);
        }
        CP_COMMIT();
    };

    // =================== GEMM1: H = relu(X @ W1 + b1) ===================
    float acc1[2][8][4];
    #pragma unroll
    for (int mi = 0; mi < 2; mi++)
        #pragma unroll
        for (int ni = 0; ni < 8; ni++)
            #pragma unroll
            for (int r = 0; r < 4; r++) acc1[mi][ni][r] = 0.0f;

    issue1(0); issue1(1);
    for (int kc = 0; kc < 12; kc++) {
        if (kc < 11) CP_WAIT(1); else CP_WAIT(0);
        __syncthreads();
        if (kc + 2 < 12) issue1(kc + 2);
        {
            const uint32_t Ab = sb + SM_U + OFF_A1 + (uint32_t)(kc % 3) * A1_BUF;
            const uint32_t Bb = sb + SM_U + OFF_B1 + (uint32_t)(kc % 3) * B1_BUF;
            #pragma unroll
            for (int ks = 0; ks < 2; ks++) {
                int k0 = ks * 16;
                uint32_t a[2][4];
                #pragma unroll
                for (int mi = 0; mi < 2; mi++) {
                    uint32_t ad = Ab + (uint32_t)((mb + mi * 16 + arow) * SA + k0 + akh) * 2;
                    LDSM4(a[mi], ad);
                }
                uint32_t b[8][2];
                #pragma unroll
                for (int p = 0; p < 4; p++) {
                    uint32_t r4[4];
                    uint32_t bd = Bb + (uint32_t)((nb1 + p * 16 + brow) * SB1T + k0 + bkh) * 2;
                    LDSM4(r4, bd);
                    b[2 * p][0] = r4[0]; b[2 * p][1] = r4[1];
                    b[2 * p + 1][0] = r4[2]; b[2 * p + 1][1] = r4[3];
                }
                #pragma unroll
                for (int mi = 0; mi < 2; mi++)
                    #pragma unroll
                    for (int ni = 0; ni < 8; ni++)
                        MMA_F16(acc1[mi][ni], a[mi], b[ni]);
            }
        }
    }
    __syncthreads();

    // prefetch W2; write H (fp16) over A1/B1 region
    issue2(0); issue2(1);
    {
        __half* Hs = (__half*)(smem + SM_U);
        #pragma unroll
        for (int mi = 0; mi < 2; mi++) {
            #pragma unroll
            for (int ni = 0; ni < 8; ni++) {
                int k  = nb1 + ni * 8 + 2 * t4;
                int m0 = mb + mi * 16 + g;
                float v0 = fmaxf(acc1[mi][ni][0] + P[k],     0.0f);
                float v1 = fmaxf(acc1[mi][ni][1] + P[k + 1], 0.0f);
                float v2 = fmaxf(acc1[mi][ni][2] + P[k],     0.0f);
                float v3 = fmaxf(acc1[mi][ni][3] + P[k + 1], 0.0f);
                __half2 h0 = __floats2half2_rn(v0, v1);
                __half2 h1 = __floats2half2_rn(v2, v3);
                *(__half2*)&Hs[m0 * SH + k]       = h0;
                *(__half2*)&Hs[(m0 + 8) * SH + k] = h1;
            }
        }
    }
    __syncthreads();

    // =================== GEMM2: O = H @ W2 ===================
    float acc2[2][4][4];
    #pragma unroll
    for (int mi = 0; mi < 2; mi++)
        #pragma unroll
        for (int ni = 0; ni < 4; ni++)
            #pragma unroll
            for (int r = 0; r < 4; r++) acc2[mi][ni][r] = 0.0f;

    const uint32_t Hb = sb + SM_U;
    for (int kc = 0; kc < 8; kc++) {
        if (kc < 7) CP_WAIT(1); else CP_WAIT(0);
        __syncthreads();
        if (kc + 2 < 8) issue2(kc + 2);
        {
            const uint32_t Bb = sb + SM_B2 + (uint32_t)(kc % 3) * B2_BUF;
            #pragma unroll
            for (int ks = 0; ks < 2; ks++) {
                int k0g = kc * 32 + ks * 16;
                int k0  = ks * 16;
                uint32_t a[2][4];
                #pragma unroll
                for (int mi = 0; mi < 2; mi++) {
                    uint32_t ad = Hb + (uint32_t)((mb + mi * 16 + arow) * SH + k0g + akh) * 2;
                    LDSM4(a[mi], ad);
                }
                uint32_t b[4][2];
                #pragma unroll
                for (int p = 0; p < 2; p++) {
                    uint32_t r4[4];
                    uint32_t bd = Bb + (uint32_t)((nb2 + p * 16 + brow) * SB2T + k0 + bkh) * 2;
                    LDSM4(r4, bd);
                    b[2 * p][0] = r4[0]; b[2 * p][1] = r4[1];
                    b[2 * p + 1][0] = r4[2]; b[2 * p + 1][1] = r4[3];
                }
                #pragma unroll
                for (int mi = 0; mi < 2; mi++)
                    #pragma unroll
                    for (int ni = 0; ni < 4; ni++)
                        MMA_F16(acc2[mi][ni], a[mi], b[ni]);
            }
        }
    }
    __syncthreads();  // H dead; Os reuses region

    // =================== Epilogue: +b2, LayerNorm, store ===================
    float* Os = (float*)(smem + SM_U);
    #pragma unroll
    for (int mi = 0; mi < 2; mi++) {
        #pragma unroll
        for (int ni = 0; ni < 4; ni++) {
            int c  = nb2 + ni * 8 + 2 * t4;
            int m0 = mb + mi * 16 + g;
            *(float2*)&Os[m0 * SOS + c]       = make_float2(acc2[mi][ni][0], acc2[mi][ni][1]);
            *(float2*)&Os[(m0 + 8) * SOS + c] = make_float2(acc2[mi][ni][2], acc2[mi][ni][3]);
        }
    }
    __syncthreads();

    // LayerNorm: 4 threads per row (64 rows), quad shuffle reduce
    {
        int row = tid >> 2, q = tid & 3;
        float vals[32];
        float sum = 0.0f, sq = 0.0f;
        #pragma unroll
        for (int c4 = 0; c4 < 8; c4++) {
            int cb = q * 32 + c4 * 4;
            float4 v = *(float4*)&Os[row * SOS + cb];
            v.x += P[256 + cb + 0]; v.y += P[256 + cb + 1];
            v.z += P[256 + cb + 2]; v.w += P[256 + cb + 3];
            vals[c4 * 4 + 0] = v.x; vals[c4 * 4 + 1] = v.y;
            vals[c4 * 4 + 2] = v.z; vals[c4 * 4 + 3] = v.w;
            sum += v.x + v.y + v.z + v.w;
            sq  += v.x * v.x + v.y * v.y + v.z * v.z + v.w * v.w;
        }
        sum += __shfl_xor_sync(0xFFFFFFFF, sum, 1);
        sq  += __shfl_xor_sync(0xFFFFFFFF, sq,  1);
        sum += __shfl_xor_sync(0xFFFFFFFF, sum, 2);
        sq  += __shfl_xor_sync(0xFFFFFFFF, sq,  2);
        float mu  = sum * (1.0f / 128.0f);
        float var = sq * (1.0f / 128.0f) - mu * mu;
        float rs  = rsqrtf(var + 1e-5f);
        #pragma unroll
        for (int c4 = 0; c4 < 8; c4++) {
            int cb = q * 32 + c4 * 4;
            float4 w;
            w.x = (vals[c4 * 4 + 0] - mu) * rs * P[384 + cb + 0] + P[512 + cb + 0];
            w.y = (vals[c4 * 4 + 1] - mu) * rs * P[384 + cb + 1] + P[512 + cb + 1];
            w.z = (vals[c4 * 4 + 2] - mu) * rs * P[384 + cb + 2] + P[512 + cb + 2];
            w.w = (vals[c4 * 4 + 3] - mu) * rs * P[384 + cb + 3] + P[512 + cb + 3];
            *(float4*)&Os[row * SOS + cb] = w;
        }
    }
    __syncthreads();

    // coalesced float4 store: 64 rows x 32 float4
    {
        float4* o4 = (float4*)out;
        #pragma unroll
        for (int i = 0; i < 8; i++) {
            int f = tid + i * NTH;
            int row = f >> 5, c4 = f & 31;
            int e = ebase + row;
            if (e < E_CNT)
                o4[(size_t)e * 32 + c4] = *(float4*)&Os[row * SOS + c4 * 4];
        }
    }
}

extern "C" void kernel_launch(void* const* d_in, const int* in_sizes, int n_in,
                              void* d_out, int out_size) {
    const float* node_attr = (const float*)d_in[0];
    const float* edge_attr = (const float*)d_in[1];
    const int*   edge_idx  = (const int*)d_in[2];
    const float* W1 = (const float*)d_in[3];
    const float* b1 = (const float*)d_in[4];
    const float* W2 = (const float*)d_in[5];
    const float* b2 = (const float*)d_in[6];
    const float* g  = (const float*)d_in[7];
    const float* be = (const float*)d_in[8];
    float* out = (float*)d_out;

    prep_kernel<<<4096, 256>>>(W1, W2, node_attr, edge_attr);

    cudaFuncSetAttribute(edge_mlp_kernel,
                         cudaFuncAttributeMaxDynamicSharedMemorySize, SM_TOTAL);
    edge_mlp_kernel<<<NCTA, NTH, SM_TOTAL>>>(edge_idx, b1, b2, g, be, out);
}

// round 8
// speedup vs baseline: 2.0209x; 1.2184x over previous
#include <cuda_runtime.h>
#include <cuda_fp16.h>
#include <cstdint>

#define E_CNT   300000
#define MTILE   64
#define NTH     256
#define NCTA    ((E_CNT + MTILE - 1) / MTILE)

// ---- strides ----
#define SA   40     // A rows, halfwords (32 k + pad)
#define SB1T 40
#define SB2T 40
#define SH   264    // H rows, halfwords (256 k + pad), 528B = 33x16B

// ---- smem byte offsets ----
#define SM_IDX   0                  // 128 ints = 512
#define SM_PAR   512                // 640 floats -> ends 3072
#define SM_B2    3072               // 3 x 128*40*2 = 30720 -> ends 33792 ; reused as LN-reduce buf
#define SM_U     33792
#define OFF_A1   0                  // 3 x 64*40*2  = 15360
#define OFF_B1   15360              // 3 x 256*40*2 = 61440 -> ends 76800
#define A1_BUF   5120
#define B1_BUF   20480
#define B2_BUF   10240
#define SM_TOTAL 110592

// fp16 scratch: weights pre-transposed to n-major
__device__ __half g_W1h[256 * 384];      // [n][k]
__device__ __half g_W2h[128 * 256];      // [n][k]
__device__ __half g_node16[50000 * 128];
__device__ __half g_edge16[300000 * 128];

static __device__ __forceinline__ uint32_t smem_u32(const void* p) {
    uint32_t a;
    asm("{ .reg .u64 t; cvta.to.shared.u64 t, %1; cvt.u32.u64 %0, t; }" : "=r"(a) : "l"(p));
    return a;
}
static __device__ __forceinline__ void cp16(uint32_t dst, const void* src) {
    asm volatile("cp.async.cg.shared.global [%0], [%1], 16;" :: "r"(dst), "l"(src));
}
#define CP_COMMIT() asm volatile("cp.async.commit_group;" ::: "memory")
#define CP_WAIT(n)  asm volatile("cp.async.wait_group %0;" :: "n"(n) : "memory")

#define LDSM4(r, addr)                                                        \
    asm volatile("ldmatrix.sync.aligned.m8n8.x4.shared.b16 {%0,%1,%2,%3}, [%4];" \
        : "=r"((r)[0]), "=r"((r)[1]), "=r"((r)[2]), "=r"((r)[3]) : "r"(addr))

#define STSM4(addr, r0, r1, r2, r3)                                           \
    asm volatile("stmatrix.sync.aligned.m8n8.x4.shared.b16 [%0], {%1,%2,%3,%4};" \
        :: "r"(addr), "r"(r0), "r"(r1), "r"(r2), "r"(r3) : "memory")

#define MMA_F16(d, a, b)                                                      \
    asm volatile("mma.sync.aligned.m16n8k16.row.col.f32.f16.f16.f32 "         \
        "{%0,%1,%2,%3}, {%4,%5,%6,%7}, {%8,%9}, {%0,%1,%2,%3};"               \
        : "+f"((d)[0]), "+f"((d)[1]), "+f"((d)[2]), "+f"((d)[3])              \
        : "r"((a)[0]), "r"((a)[1]), "r"((a)[2]), "r"((a)[3]),                 \
          "r"((b)[0]), "r"((b)[1]))

// ---------------- prep: fp16-convert node/edge tables; convert+transpose weights ----------------
__global__ void __launch_bounds__(256)
prep_kernel(const float* __restrict__ W1,
            const float* __restrict__ W2,
            const float* __restrict__ nat,
            const float* __restrict__ eat) {
    int t = blockIdx.x * blockDim.x + threadIdx.x;
    int stride = gridDim.x * blockDim.x;
    const int NW1 = 384 * 256, NW2 = 256 * 128;
    const int NND = 50000 * 128 / 4, NED = 300000 * 128 / 4;
    for (int i = t; i < NW1; i += stride) {
        int k = i >> 8, n = i & 255;
        g_W1h[n * 384 + k] = __float2half_rn(W1[i]);
    }
    for (int i = t; i < NW2; i += stride) {
        int k = i >> 7, n = i & 127;
        g_W2h[n * 256 + k] = __float2half_rn(W2[i]);
    }
    for (int i = t; i < NND; i += stride) {
        float4 v = ((const float4*)nat)[i];
        __half2 h0 = __floats2half2_rn(v.x, v.y);
        __half2 h1 = __floats2half2_rn(v.z, v.w);
        uint2 u = { *(uint32_t*)&h0, *(uint32_t*)&h1 };
        ((uint2*)g_node16)[i] = u;
    }
    for (int i = t; i < NED; i += stride) {
        float4 v = ((const float4*)eat)[i];
        __half2 h0 = __floats2half2_rn(v.x, v.y);
        __half2 h1 = __floats2half2_rn(v.z, v.w);
        uint2 u = { *(uint32_t*)&h0, *(uint32_t*)&h1 };
        ((uint2*)g_edge16)[i] = u;
    }
}

static __device__ __forceinline__ uint32_t pack_h2(float a, float b) {
    __half2 h = __floats2half2_rn(a, b);
    return *(uint32_t*)&h;
}

// ---------------- fused edge MLP (fp16 tensor path) ----------------
__global__ void __launch_bounds__(NTH, 2)
edge_mlp_kernel(const int*   __restrict__ edge_index,
                const float* __restrict__ b1,
                const float* __restrict__ b2,
                const float* __restrict__ gamma_,
                const float* __restrict__ beta_,
                float* __restrict__ out)
{
    extern __shared__ char smem[];
    const uint32_t sb = smem_u32(smem);
    const int tid = threadIdx.x;
    const int wid = tid >> 5, lid = tid & 31;
    const int g = lid >> 2, t4 = lid & 3;
    const int ebase = blockIdx.x * MTILE;

    // ldmatrix selectors (tile id = lid>>3)
    const int sel  = lid >> 3;
    const int arow = (sel & 1) * 8 + (lid & 7);   // A: m-half
    const int akh  = (sel >> 1) * 8;              // A: k-half (halfwords)
    const int brow = (sel >> 1) * 8 + (lid & 7);  // B: n-half
    const int bkh  = (sel & 1) * 8;               // B: k-half
    // stmatrix selector: tile t = lid>>3, row within tile = lid&7
    const int srow = (sel >> 1) * 16 + (sel & 1) * 8 + (lid & 7);

    int*   sidx = (int*)(smem + SM_IDX);
    float* P    = (float*)(smem + SM_PAR);

    {
        if (tid < 128) {
            int r = tid & 63, half = tid >> 6;
            int e = ebase + r; if (e >= E_CNT) e = E_CNT - 1;
            sidx[half * 64 + r] = edge_index[half * E_CNT + e];
        }
        P[tid] = b1[tid];
        if (tid < 128) {
            P[256 + tid] = b2[tid];
            P[384 + tid] = gamma_[tid];
            P[512 + tid] = beta_[tid];
        }
    }
    __syncthreads();

    const int mb  = (wid >> 2) * 32;   // 2 warps along M (tile 32)
    const int nb1 = (wid & 3) * 64;    // GEMM1: 4 warps along N (tile 64)
    const int nb2 = (wid & 3) * 32;    // GEMM2: tile 32

    auto issue1 = [&](int kc) {
        int buf = kc % 3;
        int src = kc >> 2, koff = (kc & 3) * 32;
        uint32_t abase = sb + SM_U + OFF_A1 + (uint32_t)buf * A1_BUF;
        uint32_t bbase = sb + SM_U + OFF_B1 + (uint32_t)buf * B1_BUF;
        {   // A: 64 rows x 4 x 16B -> 1 per thread
            int r = tid >> 2, c = tid & 3;
            const __half* sp;
            if (src == 0)      sp = g_node16 + (size_t)sidx[r] * 128 + koff;
            else if (src == 1) sp = g_node16 + (size_t)sidx[64 + r] * 128 + koff;
            else { int e = ebase + r; if (e >= E_CNT) e = E_CNT - 1;
                   sp = g_edge16 + (size_t)e * 128 + koff; }
            cp16(abase + (uint32_t)(r * SA + c * 8) * 2, sp + c * 8);
        }
        #pragma unroll
        for (int i = 0; i < 4; i++) {   // B1: 256 rows x 4 x 16B -> 4 per thread
            int f = tid + i * NTH;
            int n = f >> 2, c = f & 3;
            cp16(bbase + (uint32_t)(n * SB1T + c * 8) * 2,
                 g_W1h + (size_t)n * 384 + kc * 32 + c * 8);
        }
        CP_COMMIT();
    };
    auto issue2 = [&](int kc) {
        int buf = kc % 3;
        uint32_t bbase = sb + SM_B2 + (uint32_t)buf * B2_BUF;
        #pragma unroll
        for (int i = 0; i < 2; i++) {   // B2: 128 rows x 4 x 16B -> 2 per thread
            int f = tid + i * NTH;
            int n = f >> 2, c = f & 3;
            cp16(bbase + (uint32_t)(n * SB2T + c * 8) * 2,
                 g_W2h + (size_t)n * 256 + kc * 32 + c * 8);
        }
        CP_COMMIT();
    };

    // =================== GEMM1: H = relu(X @ W1 + b1) ===================
    float acc1[2][8][4];
    #pragma unroll
    for (int mi = 0; mi < 2; mi++)
        #pragma unroll
        for (int ni = 0; ni < 8; ni++)
            #pragma unroll
            for (int r = 0; r < 4; r++) acc1[mi][ni][r] = 0.0f;

    issue1(0); issue1(1);
    for (int kc = 0; kc < 12; kc++) {
        if (kc < 11) CP_WAIT(1); else CP_WAIT(0);
        __syncthreads();
        if (kc + 2 < 12) issue1(kc + 2);
        {
            const uint32_t Ab = sb + SM_U + OFF_A1 + (uint32_t)(kc % 3) * A1_BUF;
            const uint32_t Bb = sb + SM_U + OFF_B1 + (uint32_t)(kc % 3) * B1_BUF;
            #pragma unroll
            for (int ks = 0; ks < 2; ks++) {
                int k0 = ks * 16;
                uint32_t a[2][4];
                #pragma unroll
                for (int mi = 0; mi < 2; mi++) {
                    uint32_t ad = Ab + (uint32_t)((mb + mi * 16 + arow) * SA + k0 + akh) * 2;
                    LDSM4(a[mi], ad);
                }
                uint32_t b[8][2];
                #pragma unroll
                for (int p = 0; p < 4; p++) {
                    uint32_t r4[4];
                    uint32_t bd = Bb + (uint32_t)((nb1 + p * 16 + brow) * SB1T + k0 + bkh) * 2;
                    LDSM4(r4, bd);
                    b[2 * p][0] = r4[0]; b[2 * p][1] = r4[1];
                    b[2 * p + 1][0] = r4[2]; b[2 * p + 1][1] = r4[3];
                }
                #pragma unroll
                for (int mi = 0; mi < 2; mi++)
                    #pragma unroll
                    for (int ni = 0; ni < 8; ni++)
                        MMA_F16(acc1[mi][ni], a[mi], b[ni]);
            }
        }
    }
    __syncthreads();

    // prefetch W2; write H (fp16) over A1/B1 region via stmatrix
    issue2(0); issue2(1);
    {
        const uint32_t Hb = sb + SM_U;
        #pragma unroll
        for (int ni = 0; ni < 8; ni++) {
            int k = nb1 + ni * 8 + 2 * t4;   // bias col for this thread's c0/c1
            float bv0 = P[k], bv1 = P[k + 1];
            uint32_t r0 = pack_h2(fmaxf(acc1[0][ni][0] + bv0, 0.0f),
                                  fmaxf(acc1[0][ni][1] + bv1, 0.0f));
            uint32_t r1 = pack_h2(fmaxf(acc1[0][ni][2] + bv0, 0.0f),
                                  fmaxf(acc1[0][ni][3] + bv1, 0.0f));
            uint32_t r2 = pack_h2(fmaxf(acc1[1][ni][0] + bv0, 0.0f),
                                  fmaxf(acc1[1][ni][1] + bv1, 0.0f));
            uint32_t r3 = pack_h2(fmaxf(acc1[1][ni][2] + bv0, 0.0f),
                                  fmaxf(acc1[1][ni][3] + bv1, 0.0f));
            uint32_t ad = Hb + (uint32_t)((mb + srow) * SH + nb1 + ni * 8) * 2;
            STSM4(ad, r0, r1, r2, r3);
        }
    }
    __syncthreads();

    // =================== GEMM2: O = H @ W2 ===================
    float acc2[2][4][4];
    #pragma unroll
    for (int mi = 0; mi < 2; mi++)
        #pragma unroll
        for (int ni = 0; ni < 4; ni++)
            #pragma unroll
            for (int r = 0; r < 4; r++) acc2[mi][ni][r] = 0.0f;

    const uint32_t Hb = sb + SM_U;
    for (int kc = 0; kc < 8; kc++) {
        if (kc < 7) CP_WAIT(1); else CP_WAIT(0);
        __syncthreads();
        if (kc + 2 < 8) issue2(kc + 2);
        {
            const uint32_t Bb = sb + SM_B2 + (uint32_t)(kc % 3) * B2_BUF;
            #pragma unroll
            for (int ks = 0; ks < 2; ks++) {
                int k0g = kc * 32 + ks * 16;
                int k0  = ks * 16;
                uint32_t a[2][4];
                #pragma unroll
                for (int mi = 0; mi < 2; mi++) {
                    uint32_t ad = Hb + (uint32_t)((mb + mi * 16 + arow) * SH + k0g + akh) * 2;
                    LDSM4(a[mi], ad);
                }
                uint32_t b[4][2];
                #pragma unroll
                for (int p = 0; p < 2; p++) {
                    uint32_t r4[4];
                    uint32_t bd = Bb + (uint32_t)((nb2 + p * 16 + brow) * SB2T + k0 + bkh) * 2;
                    LDSM4(r4, bd);
                    b[2 * p][0] = r4[0]; b[2 * p][1] = r4[1];
                    b[2 * p + 1][0] = r4[2]; b[2 * p + 1][1] = r4[3];
                }
                #pragma unroll
                for (int mi = 0; mi < 2; mi++)
                    #pragma unroll
                    for (int ni = 0; ni < 4; ni++)
                        MMA_F16(acc2[mi][ni], a[mi], b[ni]);
            }
        }
    }

    // =================== Epilogue: +b2, LayerNorm from registers, direct store ===================
    // red[row][warpN] = float2(sum, sumsq) ; 64 x 4 x 8B = 2KB at SM_B2 (B2 stages dead:
    // last chunk used buf 1; red occupies [0, 2048) of buf 0, written only after all
    // warps pass the kc=7 barrier and finish their MMAs -> guarded by sync below).
    float2* red = (float2*)(smem + SM_B2);
    {
        // add b2, accumulate per-thread partials over this warp's 8 cols per row-slot
        float s[4], q[4];
        #pragma unroll
        for (int mi = 0; mi < 2; mi++) {
            #pragma unroll
            for (int h = 0; h < 2; h++) { s[mi * 2 + h] = 0.0f; q[mi * 2 + h] = 0.0f; }
        }
        #pragma unroll
        for (int mi = 0; mi < 2; mi++)
            #pragma unroll
            for (int ni = 0; ni < 4; ni++) {
                int c = nb2 + ni * 8 + 2 * t4;
                float bv0 = P[256 + c], bv1 = P[256 + c + 1];
                acc2[mi][ni][0] += bv0; acc2[mi][ni][1] += bv1;
                acc2[mi][ni][2] += bv0; acc2[mi][ni][3] += bv1;
                #pragma unroll
                for (int h = 0; h < 2; h++) {
                    float v0 = acc2[mi][ni][2 * h], v1 = acc2[mi][ni][2 * h + 1];
                    s[mi * 2 + h] += v0 + v1;
                    q[mi * 2 + h] += v0 * v0 + v1 * v1;
                }
            }
        // reduce over t4 (lanes xor 1,2 differ only in t4)
        #pragma unroll
        for (int j = 0; j < 4; j++) {
            s[j] += __shfl_xor_sync(0xFFFFFFFF, s[j], 1);
            q[j] += __shfl_xor_sync(0xFFFFFFFF, q[j], 1);
            s[j] += __shfl_xor_sync(0xFFFFFFFF, s[j], 2);
            q[j] += __shfl_xor_sync(0xFFFFFFFF, q[j], 2);
        }
        __syncthreads();   // all warps done with B2 stage reads before red writes
        if (t4 == 0) {
            #pragma unroll
            for (int mi = 0; mi < 2; mi++)
                #pragma unroll
                for (int h = 0; h < 2; h++) {
                    int row = mb + mi * 16 + h * 8 + g;
                    red[row * 4 + (wid & 3)] = make_float2(s[mi * 2 + h], q[mi * 2 + h]);
                }
        }
    }
    __syncthreads();

    // normalize + store direct to gmem
    {
        #pragma unroll
        for (int mi = 0; mi < 2; mi++) {
            #pragma unroll
            for (int h = 0; h < 2; h++) {
                int row = mb + mi * 16 + h * 8 + g;
                float2 p0 = red[row * 4 + 0], p1 = red[row * 4 + 1];
                float2 p2 = red[row * 4 + 2], p3 = red[row * 4 + 3];
                float S = p0.x + p1.x + p2.x + p3.x;
                float Q = p0.y + p1.y + p2.y + p3.y;
                float mu  = S * (1.0f / 128.0f);
                float var = Q * (1.0f / 128.0f) - mu * mu;
                float rs  = rsqrtf(var + 1e-5f);
                int e = ebase + row;
                if (e < E_CNT) {
                    float* orow = out + (size_t)e * 128;
                    #pragma unroll
                    for (int ni = 0; ni < 4; ni++) {
                        int c = nb2 + ni * 8 + 2 * t4;
                        float v0 = acc2[mi][ni][2 * h], v1 = acc2[mi][ni][2 * h + 1];
                        float2 w;
                        w.x = (v0 - mu) * rs * P[384 + c]     + P[512 + c];
                        w.y = (v1 - mu) * rs * P[384 + c + 1] + P[512 + c + 1];
                        *(float2*)(orow + c) = w;
                    }
                }
            }
        }
    }
}

extern "C" void kernel_launch(void* const* d_in, const int* in_sizes, int n_in,
                              void* d_out, int out_size) {
    const float* node_attr = (const float*)d_in[0];
    const float* edge_attr = (const float*)d_in[1];
    const int*   edge_idx  = (const int*)d_in[2];
    const float* W1 = (const float*)d_in[3];
    const float* b1 = (const float*)d_in[4];
    const float* W2 = (const float*)d_in[5];
    const float* b2 = (const float*)d_in[6];
    const float* g  = (const float*)d_in[7];
    const float* be = (const float*)d_in[8];
    float* out = (float*)d_out;

    prep_kernel<<<4096, 256>>>(W1, W2, node_attr, edge_attr);

    cudaFuncSetAttribute(edge_mlp_kernel,
                         cudaFuncAttributeMaxDynamicSharedMemorySize, SM_TOTAL);
    edge_mlp_kernel<<<NCTA, NTH, SM_TOTAL>>>(edge_idx, b1, b2, g, be, out);
}

// round 13
// speedup vs baseline: 2.1573x; 1.0675x over previous
#include <cuda_runtime.h>
#include <cuda_fp16.h>
#include <cstdint>

#define E_CNT   300000
#define MTILE   64
#define NTH     256
#define NCTA    ((E_CNT + MTILE - 1) / MTILE)

// ---- strides ----
#define SA   40     // A rows, halfwords (32 k + pad)
#define SB1T 40
#define SB2T 40
#define SH   264    // H rows, halfwords (256 k + pad)

// ---- smem byte offsets ----
#define SM_IDX   0                  // 128 ints = 512
#define SM_PAR   512                // 640 floats -> ends 3072
#define SM_B2    3072               // 3 x 128*40*2 = 30720 -> ends 33792 ; reused as LN-reduce buf
#define SM_U     33792
#define OFF_A1   0                  // 3 x 64*40*2  = 15360
#define OFF_B1   15360              // 3 x 256*40*2 = 61440 -> ends 76800
#define A1_BUF   5120
#define B1_BUF   20480
#define B2_BUF   10240
#define SM_TOTAL 110592

// fp16 scratch: weights pre-transposed to n-major; node table converted (edge handled in-kernel)
__device__ __half g_W1h[256 * 384];      // [n][k]
__device__ __half g_W2h[128 * 256];      // [n][k]
__device__ __half g_node16[50000 * 128];

static __device__ __forceinline__ uint32_t smem_u32(const void* p) {
    uint32_t a;
    asm("{ .reg .u64 t; cvta.to.shared.u64 t, %1; cvt.u32.u64 %0, t; }" : "=r"(a) : "l"(p));
    return a;
}
static __device__ __forceinline__ void cp16(uint32_t dst, const void* src) {
    asm volatile("cp.async.cg.shared.global [%0], [%1], 16;" :: "r"(dst), "l"(src));
}
#define CP_COMMIT() asm volatile("cp.async.commit_group;" ::: "memory")
#define CP_WAIT(n)  asm volatile("cp.async.wait_group %0;" :: "n"(n) : "memory")

#define LDSM4(r, addr)                                                        \
    asm volatile("ldmatrix.sync.aligned.m8n8.x4.shared.b16 {%0,%1,%2,%3}, [%4];" \
        : "=r"((r)[0]), "=r"((r)[1]), "=r"((r)[2]), "=r"((r)[3]) : "r"(addr))

#define STSM4(addr, r0, r1, r2, r3)                                           \
    asm volatile("stmatrix.sync.aligned.m8n8.x4.shared.b16 [%0], {%1,%2,%3,%4};" \
        :: "r"(addr), "r"(r0), "r"(r1), "r"(r2), "r"(r3) : "memory")

#define MMA_F16(d, a, b)                                                      \
    asm volatile("mma.sync.aligned.m16n8k16.row.col.f32.f16.f16.f32 "         \
        "{%0,%1,%2,%3}, {%4,%5,%6,%7}, {%8,%9}, {%0,%1,%2,%3};"               \
        : "+f"((d)[0]), "+f"((d)[1]), "+f"((d)[2]), "+f"((d)[3])              \
        : "r"((a)[0]), "r"((a)[1]), "r"((a)[2]), "r"((a)[3]),                 \
          "r"((b)[0]), "r"((b)[1]))

// ---------------- prep: fp16-convert node table; convert+transpose weights ----------------
__global__ void __launch_bounds__(256)
prep_kernel(const float* __restrict__ W1,
            const float* __restrict__ W2,
            const float* __restrict__ nat) {
    int t = blockIdx.x * blockDim.x + threadIdx.x;
    int stride = gridDim.x * blockDim.x;
    const int NW1 = 384 * 256, NW2 = 256 * 128;
    const int NND = 50000 * 128 / 4;
    for (int i = t; i < NW1; i += stride) {
        int k = i >> 8, n = i & 255;
        g_W1h[n * 384 + k] = __float2half_rn(W1[i]);
    }
    for (int i = t; i < NW2; i += stride) {
        int k = i >> 7, n = i & 127;
        g_W2h[n * 256 + k] = __float2half_rn(W2[i]);
    }
    for (int i = t; i < NND; i += stride) {
        float4 v = ((const float4*)nat)[i];
        __half2 h0 = __floats2half2_rn(v.x, v.y);
        __half2 h1 = __floats2half2_rn(v.z, v.w);
        uint2 u = { *(uint32_t*)&h0, *(uint32_t*)&h1 };
        ((uint2*)g_node16)[i] = u;
    }
}

static __device__ __forceinline__ uint32_t pack_h2(float a, float b) {
    __half2 h = __floats2half2_rn(a, b);
    return *(uint32_t*)&h;
}

// ---------------- fused edge MLP (fp16 tensor path) ----------------
__global__ void __launch_bounds__(NTH, 2)
edge_mlp_kernel(const float* __restrict__ edge_attr,
                const int*   __restrict__ edge_index,
                const float* __restrict__ b1,
                const float* __restrict__ b2,
                const float* __restrict__ gamma_,
                const float* __restrict__ beta_,
                float* __restrict__ out)
{
    extern __shared__ char smem[];
    const uint32_t sb = smem_u32(smem);
    const int tid = threadIdx.x;
    const int wid = tid >> 5, lid = tid & 31;
    const int g = lid >> 2, t4 = lid & 3;
    const int ebase = blockIdx.x * MTILE;

    // ldmatrix selectors (tile id = lid>>3)
    const int sel  = lid >> 3;
    const int arow = (sel & 1) * 8 + (lid & 7);   // A: m-half
    const int akh  = (sel >> 1) * 8;              // A: k-half (halfwords)
    const int brow = (sel >> 1) * 8 + (lid & 7);  // B: n-half
    const int bkh  = (sel & 1) * 8;               // B: k-half
    // stmatrix selector
    const int srow = (sel >> 1) * 16 + (sel & 1) * 8 + (lid & 7);

    int*   sidx = (int*)(smem + SM_IDX);
    float* P    = (float*)(smem + SM_PAR);

    {
        if (tid < 128) {
            int r = tid & 63, half = tid >> 6;
            int e = ebase + r; if (e >= E_CNT) e = E_CNT - 1;
            sidx[half * 64 + r] = edge_index[half * E_CNT + e];
        }
        P[tid] = b1[tid];
        if (tid < 128) {
            P[256 + tid] = b2[tid];
            P[384 + tid] = gamma_[tid];
            P[512 + tid] = beta_[tid];
        }
    }
    __syncthreads();

    const int mb  = (wid >> 2) * 32;   // 2 warps along M (tile 32)
    const int nb1 = (wid & 3) * 64;    // GEMM1: 4 warps along N (tile 64)
    const int nb2 = (wid & 3) * 32;    // GEMM2: tile 32

    // this thread's slot for edge fp32 staging (chunks 8..11)
    const int er = tid >> 2, ec = tid & 3;
    int eE = ebase + er; if (eE >= E_CNT) eE = E_CNT - 1;
    const float4* erow = (const float4*)(edge_attr + (size_t)eE * 128);

    auto issue1 = [&](int kc) {
        int buf = kc % 3;
        int src = kc >> 2, koff = (kc & 3) * 32;
        uint32_t abase = sb + SM_U + OFF_A1 + (uint32_t)buf * A1_BUF;
        uint32_t bbase = sb + SM_U + OFF_B1 + (uint32_t)buf * B1_BUF;
        if (src < 2) {   // A via cp.async only for node chunks; edge handled via LDG pipeline
            int r = tid >> 2, c = tid & 3;
            const __half* sp = (src == 0)
                ? g_node16 + (size_t)sidx[r] * 128 + koff
                : g_node16 + (size_t)sidx[64 + r] * 128 + koff;
            cp16(abase + (uint32_t)(r * SA + c * 8) * 2, sp + c * 8);
        }
        #pragma unroll
        for (int i = 0; i < 4; i++) {   // B1: 256 rows x 4 x 16B -> 4 per thread
            int f = tid + i * NTH;
            int n = f >> 2, c = f & 3;
            cp16(bbase + (uint32_t)(n * SB1T + c * 8) * 2,
                 g_W1h + (size_t)n * 384 + kc * 32 + c * 8);
        }
        CP_COMMIT();
    };
    auto issue2 = [&](int kc) {
        int buf = kc % 3;
        uint32_t bbase = sb + SM_B2 + (uint32_t)buf * B2_BUF;
        #pragma unroll
        for (int i = 0; i < 2; i++) {   // B2: 128 rows x 4 x 16B -> 2 per thread
            int f = tid + i * NTH;
            int n = f >> 2, c = f & 3;
            cp16(bbase + (uint32_t)(n * SB2T + c * 8) * 2,
                 g_W2h + (size_t)n * 256 + kc * 32 + c * 8);
        }
        CP_COMMIT();
    };

    // =================== GEMM1: H = relu(X @ W1 + b1) ===================
    float acc1[2][8][4];
    #pragma unroll
    for (int mi = 0; mi < 2; mi++)
        #pragma unroll
        for (int ni = 0; ni < 8; ni++)
            #pragma unroll
            for (int r = 0; r < 4; r++) acc1[mi][ni][r] = 0.0f;

    issue1(0); issue1(1);
    for (int kc = 0; kc < 12; kc++) {
        if (kc < 11) CP_WAIT(1); else CP_WAIT(0);
        __syncthreads();
        if (kc + 2 < 12) issue1(kc + 2);

        // start fp32 LDG for edge chunk kc+2 (chunks 8..11); consumed after compute
        float4 e0, e1;
        const bool estage = (kc + 2 >= 8) && (kc + 2 < 12);
        if (estage) {
            int koff4 = ((kc + 2) & 3) * 8;        // float4 index offset within row
            e0 = erow[koff4 + ec * 2];
            e1 = erow[koff4 + ec * 2 + 1];
        }
        {
            const uint32_t Ab = sb + SM_U + OFF_A1 + (uint32_t)(kc % 3) * A1_BUF;
            const uint32_t Bb = sb + SM_U + OFF_B1 + (uint32_t)(kc % 3) * B1_BUF;
            #pragma unroll
            for (int ks = 0; ks < 2; ks++) {
                int k0 = ks * 16;
                uint32_t a[2][4];
                #pragma unroll
                for (int mi = 0; mi < 2; mi++) {
                    uint32_t ad = Ab + (uint32_t)((mb + mi * 16 + arow) * SA + k0 + akh) * 2;
                    LDSM4(a[mi], ad);
                }
                uint32_t b[8][2];
                #pragma unroll
                for (int p = 0; p < 4; p++) {
                    uint32_t r4[4];
                    uint32_t bd = Bb + (uint32_t)((nb1 + p * 16 + brow) * SB1T + k0 + bkh) * 2;
                    LDSM4(r4, bd);
                    b[2 * p][0] = r4[0]; b[2 * p][1] = r4[1];
                    b[2 * p + 1][0] = r4[2]; b[2 * p + 1][1] = r4[3];
                }
                #pragma unroll
                for (int mi = 0; mi < 2; mi++)
                    #pragma unroll
                    for (int ni = 0; ni < 8; ni++)
                        MMA_F16(acc1[mi][ni], a[mi], b[ni]);
            }
        }
        // convert + store staged edge data into A tile of chunk kc+2
        if (estage) {
            uint32_t abase = sb + SM_U + OFF_A1 + (uint32_t)((kc + 2) % 3) * A1_BUF;
            uint4 u;
            u.x = pack_h2(e0.x, e0.y); u.y = pack_h2(e0.z, e0.w);
            u.z = pack_h2(e1.x, e1.y); u.w = pack_h2(e1.z, e1.w);
            *(uint4*)(smem + (abase - sb) + (uint32_t)(er * SA + ec * 8) * 2) = u;
        }
    }
    __syncthreads();

    // prefetch W2; write H (fp16) over A1/B1 region via stmatrix
    issue2(0); issue2(1);
    {
        const uint32_t Hb = sb + SM_U;
        #pragma unroll
        for (int ni = 0; ni < 8; ni++) {
            int k = nb1 + ni * 8 + 2 * t4;
            float bv0 = P[k], bv1 = P[k + 1];
            uint32_t r0 = pack_h2(fmaxf(acc1[0][ni][0] + bv0, 0.0f),
                                  fmaxf(acc1[0][ni][1] + bv1, 0.0f));
            uint32_t r1 = pack_h2(fmaxf(acc1[0][ni][2] + bv0, 0.0f),
                                  fmaxf(acc1[0][ni][3] + bv1, 0.0f));
            uint32_t r2 = pack_h2(fmaxf(acc1[1][ni][0] + bv0, 0.0f),
                                  fmaxf(acc1[1][ni][1] + bv1, 0.0f));
            uint32_t r3 = pack_h2(fmaxf(acc1[1][ni][2] + bv0, 0.0f),
                                  fmaxf(acc1[1][ni][3] + bv1, 0.0f));
            uint32_t ad = Hb + (uint32_t)((mb + srow) * SH + nb1 + ni * 8) * 2;
            STSM4(ad, r0, r1, r2, r3);
        }
    }
    __syncthreads();

    // =================== GEMM2: O = H @ W2 ===================
    float acc2[2][4][4];
    #pragma unroll
    for (int mi = 0; mi < 2; mi++)
        #pragma unroll
        for (int ni = 0; ni < 4; ni++)
            #pragma unroll
            for (int r = 0; r < 4; r++) acc2[mi][ni][r] = 0.0f;

    const uint32_t Hb = sb + SM_U;
    for (int kc = 0; kc < 8; kc++) {
        if (kc < 7) CP_WAIT(1); else CP_WAIT(0);
        __syncthreads();
        if (kc + 2 < 8) issue2(kc + 2);
        {
            const uint32_t Bb = sb + SM_B2 + (uint32_t)(kc % 3) * B2_BUF;
            #pragma unroll
            for (int ks = 0; ks < 2; ks++) {
                int k0g = kc * 32 + ks * 16;
                int k0  = ks * 16;
                uint32_t a[2][4];
                #pragma unroll
                for (int mi = 0; mi < 2; mi++) {
                    uint32_t ad = Hb + (uint32_t)((mb + mi * 16 + arow) * SH + k0g + akh) * 2;
                    LDSM4(a[mi], ad);
                }
                uint32_t b[4][2];
                #pragma unroll
                for (int p = 0; p < 2; p++) {
                    uint32_t r4[4];
                    uint32_t bd = Bb + (uint32_t)((nb2 + p * 16 + brow) * SB2T + k0 + bkh) * 2;
                    LDSM4(r4, bd);
                    b[2 * p][0] = r4[0]; b[2 * p][1] = r4[1];
                    b[2 * p + 1][0] = r4[2]; b[2 * p + 1][1] = r4[3];
                }
                #pragma unroll
                for (int mi = 0; mi < 2; mi++)
                    #pragma unroll
                    for (int ni = 0; ni < 4; ni++)
                        MMA_F16(acc2[mi][ni], a[mi], b[ni]);
            }
        }
    }

    // =================== Epilogue: +b2, LayerNorm from registers, direct store ===================
    float2* red = (float2*)(smem + SM_B2);
    {
        float s[4], q[4];
        #pragma unroll
        for (int j = 0; j < 4; j++) { s[j] = 0.0f; q[j] = 0.0f; }
        #pragma unroll
        for (int mi = 0; mi < 2; mi++)
            #pragma unroll
            for (int ni = 0; ni < 4; ni++) {
                int c = nb2 + ni * 8 + 2 * t4;
                float bv0 = P[256 + c], bv1 = P[256 + c + 1];
                acc2[mi][ni][0] += bv0; acc2[mi][ni][1] += bv1;
                acc2[mi][ni][2] += bv0; acc2[mi][ni][3] += bv1;
                #pragma unroll
                for (int h = 0; h < 2; h++) {
                    float v0 = acc2[mi][ni][2 * h], v1 = acc2[mi][ni][2 * h + 1];
                    s[mi * 2 + h] += v0 + v1;
                    q[mi * 2 + h] += v0 * v0 + v1 * v1;
                }
            }
        #pragma unroll
        for (int j = 0; j < 4; j++) {
            s[j] += __shfl_xor_sync(0xFFFFFFFF, s[j], 1);
            q[j] += __shfl_xor_sync(0xFFFFFFFF, q[j], 1);
            s[j] += __shfl_xor_sync(0xFFFFFFFF, s[j], 2);
            q[j] += __shfl_xor_sync(0xFFFFFFFF, q[j], 2);
        }
        __syncthreads();   // all warps done with B2 stage reads before red writes
        if (t4 == 0) {
            #pragma unroll
            for (int mi = 0; mi < 2; mi++)
                #pragma unroll
                for (int h = 0; h < 2; h++) {
                    int row = mb + mi * 16 + h * 8 + g;
                    red[row * 4 + (wid & 3)] = make_float2(s[mi * 2 + h], q[mi * 2 + h]);
                }
        }
    }
    __syncthreads();

    // normalize + store direct to gmem
    {
        #pragma unroll
        for (int mi = 0; mi < 2; mi++) {
            #pragma unroll
            for (int h = 0; h < 2; h++) {
                int row = mb + mi * 16 + h * 8 + g;
                float2 p0 = red[row * 4 + 0], p1 = red[row * 4 + 1];
                float2 p2 = red[row * 4 + 2], p3 = red[row * 4 + 3];
                float S = p0.x + p1.x + p2.x + p3.x;
                float Q = p0.y + p1.y + p2.y + p3.y;
                float mu  = S * (1.0f / 128.0f);
                float var = Q * (1.0f / 128.0f) - mu * mu;
                float rs  = rsqrtf(var + 1e-5f);
                int e = ebase + row;
                if (e < E_CNT) {
                    float* orow = out + (size_t)e * 128;
                    #pragma unroll
                    for (int ni = 0; ni < 4; ni++) {
                        int c = nb2 + ni * 8 + 2 * t4;
                        float v0 = acc2[mi][ni][2 * h], v1 = acc2[mi][ni][2 * h + 1];
                        float2 w;
                        w.x = (v0 - mu) * rs * P[384 + c]     + P[512 + c];
                        w.y = (v1 - mu) * rs * P[384 + c + 1] + P[512 + c + 1];
                        *(float2*)(orow + c) = w;
                    }
                }
            }
        }
    }
}

extern "C" void kernel_launch(void* const* d_in, const int* in_sizes, int n_in,
                              void* d_out, int out_size) {
    const float* node_attr = (const float*)d_in[0];
    const float* edge_attr = (const float*)d_in[1];
    const int*   edge_idx  = (const int*)d_in[2];
    const float* W1 = (const float*)d_in[3];
    const float* b1 = (const float*)d_in[4];
    const float* W2 = (const float*)d_in[5];
    const float* b2 = (const float*)d_in[6];
    const float* g  = (const float*)d_in[7];
    const float* be = (const float*)d_in[8];
    float* out = (float*)d_out;

    prep_kernel<<<1024, 256>>>(W1, W2, node_attr);

    cudaFuncSetAttribute(edge_mlp_kernel,
                         cudaFuncAttributeMaxDynamicSharedMemorySize, SM_TOTAL);
    edge_mlp_kernel<<<NCTA, NTH, SM_TOTAL>>>(edge_attr, edge_idx, b1, b2, g, be, out);
}